// round 1
// baseline (speedup 1.0000x reference)
#include <cuda_runtime.h>
#include <math.h>

// ---- problem dims ----
#define S_   512
#define B_   2048
#define GL_  32
#define OL_  20
#define M_   32
#define C_   16
#define GM_  64
#define OM_  20
#define GR_  128
#define OR_  38
#define IM_  384      // C_*OL_ + GM_
#define IR_  768      // M_*OM_ + GR_
#define EPSF 1e-5f

// ---- scratch (static __device__, no allocations) ----
__device__ float g_leaf_h[S_ * B_ * OL_];        // raw tanh(leaf) pre-BN, [S][B][20]
__device__ float g_leaf_ac[S_ * OL_ * 2];        // (a,c) per (s,o): norm = a*h + c
__device__ float g_mid_h[B_ * M_ * OM_];         // raw tanh(mid) pre-BN, [B][M*20] (b-major!)
__device__ float g_mid_part[M_ * 8 * OM_ * 2];   // per-(m,chunk) partial (sum, sumsq)
__device__ float g_ac_root[IR_ * 2];             // (a,c) per root-input index (identity head)
__device__ float g_root_part[8 * B_ * 40];       // K-split partials, padded to 40 cols
__device__ float g_root_h[B_ * OR_];             // raw tanh(root) pre-BN
__device__ float g_root_ac[OR_ * 2];

// ============================================================================
// Kernel 1: leaf. One block per subsystem s (sees full batch -> complete BN
// stats in-block). Writes raw h and the (a,c) BN-affine coefficients.
// ============================================================================
__global__ __launch_bounds__(256) void k_leaf(
    const float* __restrict__ x_leaf, const float* __restrict__ W_leaf,
    const float* __restrict__ b_leaf, const float* __restrict__ gam,
    const float* __restrict__ bet)
{
    const int s = blockIdx.x;
    const int tid = threadIdx.x;
    __shared__ __align__(16) float sW[GL_ * OL_];
    __shared__ float sB[OL_];
    __shared__ float sRed[8 * 40];

    for (int i = tid; i < GL_ * OL_; i += 256) sW[i] = W_leaf[s * GL_ * OL_ + i];
    if (tid < OL_) sB[tid] = b_leaf[s * OL_ + tid];
    __syncthreads();

    float sum[OL_], sq[OL_];
#pragma unroll
    for (int o = 0; o < OL_; o++) { sum[o] = 0.f; sq[o] = 0.f; }

    for (int it = 0; it < B_ / 256; it++) {
        const int b = it * 256 + tid;
        const float4* xp = (const float4*)(x_leaf + ((long)s * B_ + b) * GL_);
        float x[GL_];
#pragma unroll
        for (int i4 = 0; i4 < GL_ / 4; i4++) {
            float4 v = xp[i4];
            x[i4*4+0] = v.x; x[i4*4+1] = v.y; x[i4*4+2] = v.z; x[i4*4+3] = v.w;
        }
        float acc[OL_];
#pragma unroll
        for (int o = 0; o < OL_; o++) acc[o] = sB[o];
#pragma unroll
        for (int i = 0; i < GL_; i++) {
            const float xi = x[i];
#pragma unroll
            for (int o4 = 0; o4 < OL_ / 4; o4++) {
                float4 w = *(const float4*)&sW[i * OL_ + o4 * 4];
                acc[o4*4+0] = fmaf(xi, w.x, acc[o4*4+0]);
                acc[o4*4+1] = fmaf(xi, w.y, acc[o4*4+1]);
                acc[o4*4+2] = fmaf(xi, w.z, acc[o4*4+2]);
                acc[o4*4+3] = fmaf(xi, w.w, acc[o4*4+3]);
            }
        }
        float h[OL_];
#pragma unroll
        for (int o = 0; o < OL_; o++) {
            float t = tanhf(acc[o]);
            h[o] = t; sum[o] += t; sq[o] = fmaf(t, t, sq[o]);
        }
        float4* op = (float4*)(g_leaf_h + ((long)s * B_ + b) * OL_);
#pragma unroll
        for (int o4 = 0; o4 < 5; o4++)
            op[o4] = make_float4(h[o4*4+0], h[o4*4+1], h[o4*4+2], h[o4*4+3]);
    }

    // block reduction of 20 sums + 20 sumsqs
#pragma unroll
    for (int o = 0; o < OL_; o++) {
        for (int off = 16; off > 0; off >>= 1) {
            sum[o] += __shfl_down_sync(0xffffffffu, sum[o], off);
            sq[o]  += __shfl_down_sync(0xffffffffu, sq[o],  off);
        }
    }
    const int warp = tid >> 5, lane = tid & 31;
    if (lane == 0) {
#pragma unroll
        for (int o = 0; o < OL_; o++) { sRed[warp*40+o] = sum[o]; sRed[warp*40+20+o] = sq[o]; }
    }
    __syncthreads();
    if (tid < OL_) {
        float s1 = 0.f, s2 = 0.f;
        for (int w = 0; w < 8; w++) { s1 += sRed[w*40+tid]; s2 += sRed[w*40+20+tid]; }
        const float mean = s1 * (1.f / B_);
        const float var  = s2 * (1.f / B_) - mean * mean;
        const float a = gam[s * OL_ + tid] * rsqrtf(var + EPSF);
        const float c = bet[s * OL_ + tid] - mean * a;
        g_leaf_ac[(s * OL_ + tid) * 2 + 0] = a;
        g_leaf_ac[(s * OL_ + tid) * 2 + 1] = c;
    }
}

// ============================================================================
// Kernel 2: mid. grid(8 batch-chunks, 32 mids), 256 thr, one thread per b.
// Applies leaf BN on the fly via (a,c). Writes raw h into b-major layout
// [B][M*20] (= root's concat layout) and per-chunk partial stats.
// ============================================================================
__global__ __launch_bounds__(256) void k_mid(
    const float* __restrict__ x_mid, const float* __restrict__ W_mid,
    const float* __restrict__ b_mid)
{
    const int chunk = blockIdx.x;
    const int m = blockIdx.y;
    const int tid = threadIdx.x;
    const int b = chunk * 256 + tid;

    __shared__ __align__(16) float sW[IM_ * OM_];   // 30720 B
    __shared__ __align__(16) float sA[C_ * OL_];
    __shared__ __align__(16) float sC[C_ * OL_];
    __shared__ float sB[OM_];
    __shared__ float sRed[8 * 40];

    for (int i = tid; i < IM_ * OM_; i += 256) sW[i] = W_mid[m * IM_ * OM_ + i];
    for (int i = tid; i < C_ * OL_; i += 256) {
        sA[i] = g_leaf_ac[(m * C_ * OL_ + i) * 2 + 0];
        sC[i] = g_leaf_ac[(m * C_ * OL_ + i) * 2 + 1];
    }
    if (tid < OM_) sB[tid] = b_mid[m * OM_ + tid];
    __syncthreads();

    float acc[OM_];
#pragma unroll
    for (int o = 0; o < OM_; o++) acc[o] = sB[o];

    // part 1: own genes (rows 0..63)
    const float4* xm4 = (const float4*)(x_mid + ((long)m * B_ + b) * GM_);
#pragma unroll 2
    for (int i4 = 0; i4 < GM_ / 4; i4++) {
        float4 v = xm4[i4];
        float xs[4] = { v.x, v.y, v.z, v.w };
#pragma unroll
        for (int c = 0; c < 4; c++) {
            const int i = i4 * 4 + c;
            const float xi = xs[c];
#pragma unroll
            for (int o4 = 0; o4 < 5; o4++) {
                float4 w = *(const float4*)&sW[i * OM_ + o4 * 4];
                acc[o4*4+0] = fmaf(xi, w.x, acc[o4*4+0]);
                acc[o4*4+1] = fmaf(xi, w.y, acc[o4*4+1]);
                acc[o4*4+2] = fmaf(xi, w.z, acc[o4*4+2]);
                acc[o4*4+3] = fmaf(xi, w.w, acc[o4*4+3]);
            }
        }
    }
    // part 2: 16 child leaves (rows 64..383), normalized on the fly
#pragma unroll 1
    for (int j = 0; j < C_; j++) {
        const float4* hp = (const float4*)(g_leaf_h + (((long)(m * C_ + j)) * B_ + b) * OL_);
        float xn[OL_];
#pragma unroll
        for (int e4 = 0; e4 < 5; e4++) {
            float4 h4 = hp[e4];
            float4 a4 = *(const float4*)&sA[j * OL_ + e4 * 4];
            float4 c4 = *(const float4*)&sC[j * OL_ + e4 * 4];
            xn[e4*4+0] = fmaf(h4.x, a4.x, c4.x);
            xn[e4*4+1] = fmaf(h4.y, a4.y, c4.y);
            xn[e4*4+2] = fmaf(h4.z, a4.z, c4.z);
            xn[e4*4+3] = fmaf(h4.w, a4.w, c4.w);
        }
        const int rbase = GM_ + j * OL_;
#pragma unroll
        for (int e = 0; e < OL_; e++) {
            const float xi = xn[e];
#pragma unroll
            for (int o4 = 0; o4 < 5; o4++) {
                float4 w = *(const float4*)&sW[(rbase + e) * OM_ + o4 * 4];
                acc[o4*4+0] = fmaf(xi, w.x, acc[o4*4+0]);
                acc[o4*4+1] = fmaf(xi, w.y, acc[o4*4+1]);
                acc[o4*4+2] = fmaf(xi, w.z, acc[o4*4+2]);
                acc[o4*4+3] = fmaf(xi, w.w, acc[o4*4+3]);
            }
        }
    }

    float sum[OM_], sq[OM_], h[OM_];
#pragma unroll
    for (int o = 0; o < OM_; o++) {
        float t = tanhf(acc[o]);
        h[o] = t; sum[o] = t; sq[o] = t * t;
    }
    float4* op = (float4*)(g_mid_h + (long)b * (M_ * OM_) + m * OM_);
#pragma unroll
    for (int o4 = 0; o4 < 5; o4++)
        op[o4] = make_float4(h[o4*4+0], h[o4*4+1], h[o4*4+2], h[o4*4+3]);

#pragma unroll
    for (int o = 0; o < OM_; o++) {
        for (int off = 16; off > 0; off >>= 1) {
            sum[o] += __shfl_down_sync(0xffffffffu, sum[o], off);
            sq[o]  += __shfl_down_sync(0xffffffffu, sq[o],  off);
        }
    }
    const int warp = tid >> 5, lane = tid & 31;
    if (lane == 0) {
#pragma unroll
        for (int o = 0; o < OM_; o++) { sRed[warp*40+o] = sum[o]; sRed[warp*40+20+o] = sq[o]; }
    }
    __syncthreads();
    if (tid < OM_) {
        float s1 = 0.f, s2 = 0.f;
        for (int w = 0; w < 8; w++) { s1 += sRed[w*40+tid]; s2 += sRed[w*40+20+tid]; }
        g_mid_part[((m * 8 + chunk) * OM_ + tid) * 2 + 0] = s1;
        g_mid_part[((m * 8 + chunk) * OM_ + tid) * 2 + 1] = s2;
    }
}

// ============================================================================
// Kernel 3: finalize mid BN -> (a,c) per root-input index (identity for genes)
// ============================================================================
__global__ void k_midac(const float* __restrict__ gam, const float* __restrict__ bet)
{
    const int t = threadIdx.x;  // 768 threads, 1 block
    if (t < GR_) {
        g_ac_root[t * 2 + 0] = 1.f;
        g_ac_root[t * 2 + 1] = 0.f;
    } else {
        const int idx = t - GR_;           // (m*20 + o)
        float s1 = 0.f, s2 = 0.f;
        const int mbase = (idx / OM_) * 8 * OM_ + (idx % OM_);
#pragma unroll
        for (int ch = 0; ch < 8; ch++) {
            s1 += g_mid_part[(mbase + ch * OM_) * 2 + 0];
            s2 += g_mid_part[(mbase + ch * OM_) * 2 + 1];
        }
        const float mean = s1 * (1.f / B_);
        const float var  = s2 * (1.f / B_) - mean * mean;
        const float a = gam[idx] * rsqrtf(var + EPSF);
        g_ac_root[t * 2 + 0] = a;
        g_ac_root[t * 2 + 1] = bet[idx] - mean * a;
    }
}

// ============================================================================
// Kernel 4: root GEMM, K-split. grid(8 k-chunks, 16 b-chunks), 128 thr,
// thread per b, 40 (padded) accumulators over a 96-row K slice.
// ============================================================================
__global__ __launch_bounds__(128) void k_rootp(
    const float* __restrict__ x_root, const float* __restrict__ W_root)
{
    const int kc = blockIdx.x;
    const int bc = blockIdx.y;
    const int tid = threadIdx.x;
    const int b = bc * 128 + tid;

    __shared__ __align__(16) float sW[96 * 40];
    __shared__ float sA[96], sC[96];

    for (int idx = tid; idx < 96 * 40; idx += 128) {
        const int kl = idx / 40, o = idx % 40;
        sW[idx] = (o < OR_) ? W_root[(kc * 96 + kl) * OR_ + o] : 0.f;
    }
    for (int idx = tid; idx < 96; idx += 128) {
        sA[idx] = g_ac_root[(kc * 96 + idx) * 2 + 0];
        sC[idx] = g_ac_root[(kc * 96 + idx) * 2 + 1];
    }
    __syncthreads();

    float acc[40];
#pragma unroll
    for (int o = 0; o < 40; o++) acc[o] = 0.f;

    const float4* px = (const float4*)(x_root + (long)b * GR_);
    const float4* pm = (const float4*)(g_mid_h + (long)b * (M_ * OM_));

#pragma unroll 1
    for (int kl4 = 0; kl4 < 24; kl4++) {
        const int k0 = kc * 96 + kl4 * 4;   // 128 boundary is 4-aligned per chunk
        const float4 v = (k0 < GR_) ? px[k0 >> 2] : pm[(k0 - GR_) >> 2];
        float xs[4] = { v.x, v.y, v.z, v.w };
#pragma unroll
        for (int c = 0; c < 4; c++) {
            const int kl = kl4 * 4 + c;
            const float xn = fmaf(xs[c], sA[kl], sC[kl]);
#pragma unroll
            for (int o4 = 0; o4 < 10; o4++) {
                float4 w = *(const float4*)&sW[kl * 40 + o4 * 4];
                acc[o4*4+0] = fmaf(xn, w.x, acc[o4*4+0]);
                acc[o4*4+1] = fmaf(xn, w.y, acc[o4*4+1]);
                acc[o4*4+2] = fmaf(xn, w.z, acc[o4*4+2]);
                acc[o4*4+3] = fmaf(xn, w.w, acc[o4*4+3]);
            }
        }
    }
    float4* op = (float4*)(g_root_part + ((long)kc * B_ + b) * 40);
#pragma unroll
    for (int o4 = 0; o4 < 10; o4++)
        op[o4] = make_float4(acc[o4*4+0], acc[o4*4+1], acc[o4*4+2], acc[o4*4+3]);
}

// ============================================================================
// Kernel 5: combine K-split partials + bias + tanh -> raw root h
// ============================================================================
__global__ __launch_bounds__(256) void k_rootcomb(const float* __restrict__ b_root)
{
    const int e = blockIdx.x * 256 + threadIdx.x;     // 304*256 == 2048*38 exactly
    const int b = e / OR_, o = e % OR_;
    float s = b_root[o];
#pragma unroll
    for (int kc = 0; kc < 8; kc++)
        s += g_root_part[((long)kc * B_ + b) * 40 + o];
    g_root_h[e] = tanhf(s);
}

// ============================================================================
// Kernel 6: root BN stats (one block per output column)
// ============================================================================
__global__ __launch_bounds__(256) void k_rootstats(
    const float* __restrict__ gam, const float* __restrict__ bet)
{
    const int o = blockIdx.x;
    const int tid = threadIdx.x;
    float s1 = 0.f, s2 = 0.f;
    for (int b = tid; b < B_; b += 256) {
        const float h = g_root_h[b * OR_ + o];
        s1 += h; s2 = fmaf(h, h, s2);
    }
    for (int off = 16; off > 0; off >>= 1) {
        s1 += __shfl_down_sync(0xffffffffu, s1, off);
        s2 += __shfl_down_sync(0xffffffffu, s2, off);
    }
    __shared__ float r1[8], r2[8];
    if ((tid & 31) == 0) { r1[tid >> 5] = s1; r2[tid >> 5] = s2; }
    __syncthreads();
    if (tid == 0) {
        float t1 = 0.f, t2 = 0.f;
        for (int w = 0; w < 8; w++) { t1 += r1[w]; t2 += r2[w]; }
        const float mean = t1 * (1.f / B_);
        const float var  = t2 * (1.f / B_) - mean * mean;
        const float a = gam[o] * rsqrtf(var + EPSF);
        g_root_ac[o * 2 + 0] = a;
        g_root_ac[o * 2 + 1] = bet[o] - mean * a;
    }
}

// ============================================================================
// Kernel 7: normalize root -> output
// ============================================================================
__global__ __launch_bounds__(256) void k_rootnorm(float* __restrict__ out)
{
    const int e = blockIdx.x * 256 + threadIdx.x;
    const int o = e % OR_;
    out[e] = fmaf(g_root_h[e], g_root_ac[o * 2 + 0], g_root_ac[o * 2 + 1]);
}

// ============================================================================
extern "C" void kernel_launch(void* const* d_in, const int* in_sizes, int n_in,
                              void* d_out, int out_size)
{
    const float* x_leaf = (const float*)d_in[0];
    const float* x_mid  = (const float*)d_in[1];
    const float* x_root = (const float*)d_in[2];
    const float* W_leaf = (const float*)d_in[3];
    const float* b_leaf = (const float*)d_in[4];
    const float* gleaf  = (const float*)d_in[5];
    const float* beleaf = (const float*)d_in[6];
    const float* W_mid  = (const float*)d_in[7];
    const float* b_mid  = (const float*)d_in[8];
    const float* gmid   = (const float*)d_in[9];
    const float* bemid  = (const float*)d_in[10];
    const float* W_root = (const float*)d_in[11];
    const float* b_root = (const float*)d_in[12];
    const float* groot  = (const float*)d_in[13];
    const float* beroot = (const float*)d_in[14];
    float* out = (float*)d_out;

    k_leaf<<<S_, 256>>>(x_leaf, W_leaf, b_leaf, gleaf, beleaf);
    k_mid<<<dim3(8, M_), 256>>>(x_mid, W_mid, b_mid);
    k_midac<<<1, 768>>>(gmid, bemid);
    k_rootp<<<dim3(8, 16), 128>>>(x_root, W_root);
    k_rootcomb<<<304, 256>>>(b_root);
    k_rootstats<<<OR_, 256>>>(groot, beroot);
    k_rootnorm<<<304, 256>>>(out);
}

// round 2
// speedup vs baseline: 1.0783x; 1.0783x over previous
#include <cuda_runtime.h>
#include <math.h>

// ---- problem dims ----
#define S_   512
#define B_   2048
#define GL_  32
#define OL_  20
#define M_   32
#define C_   16
#define GM_  64
#define OM_  20
#define GR_  128
#define OR_  38
#define IM_  384      // C_*OL_ + GM_
#define IR_  768      // M_*OM_ + GR_
#define EPSF 1e-5f
#define MC_  8        // mid batch chunks (256 rows each)
#define KC_  16       // root K chunks (48 rows each)

// ---- scratch ----
__device__ float g_leaf_h[S_ * B_ * OL_];        // raw tanh(leaf), [S][B][20]
__device__ float g_leaf_ac[S_ * OL_ * 2];        // (a,c): norm = a*h + c
__device__ float g_Wmid[M_ * IM_ * OM_];         // BN-folded mid weights
__device__ float g_bmid[M_ * OM_];               // BN-folded mid bias
__device__ float g_mid_h[B_ * M_ * OM_];         // raw tanh(mid), [B][M*20]
__device__ float g_mid_part[M_ * MC_ * OM_ * 2];
__device__ float g_ac_root[IR_ * 2];
__device__ float g_Wroot[IR_ * 40];              // BN-folded root weights, padded 40
__device__ float g_broot[40];
__device__ float g_root_part[KC_ * B_ * 40];
__device__ float g_root_h[B_ * OR_];
__device__ float g_root_ac[OR_ * 2];

// fast accurate tanh: 1 - 2/(exp(2x)+1), ~2e-7 abs error
__device__ __forceinline__ float ftanh(float x) {
    float e;
    asm("ex2.approx.f32 %0, %1;" : "=f"(e) : "f"(x * 2.885390081777927f));
    float r;
    asm("rcp.approx.f32 %0, %1;" : "=f"(r) : "f"(e + 1.0f));
    return fmaf(-2.f, r, 1.f);
}

// ============================================================================
// Kernel 1: leaf. One block per subsystem; 128 threads, each handles 2 batch
// rows per iter (8 iters = 2048). Full-batch BN stats in-block.
// ============================================================================
__global__ __launch_bounds__(128) void k_leaf(
    const float* __restrict__ x_leaf, const float* __restrict__ W_leaf,
    const float* __restrict__ b_leaf, const float* __restrict__ gam,
    const float* __restrict__ bet)
{
    const int s = blockIdx.x;
    const int tid = threadIdx.x;
    __shared__ __align__(16) float sW[GL_ * OL_];
    __shared__ float sB[OL_];
    __shared__ float sRed[4 * 40];

    for (int i = tid; i < GL_ * OL_; i += 128) sW[i] = W_leaf[s * GL_ * OL_ + i];
    if (tid < OL_) sB[tid] = b_leaf[s * OL_ + tid];
    __syncthreads();

    float sum[OL_], sq[OL_];
#pragma unroll
    for (int o = 0; o < OL_; o++) { sum[o] = 0.f; sq[o] = 0.f; }

#pragma unroll 1
    for (int it = 0; it < 8; it++) {
        const int b0 = it * 256 + tid;            // rows b0 and b0+128
        const float4* xp0 = (const float4*)(x_leaf + ((long)s * B_ + b0) * GL_);
        const float4* xp1 = (const float4*)(x_leaf + ((long)s * B_ + b0 + 128) * GL_);
        float acc0[OL_], acc1[OL_];
#pragma unroll
        for (int o = 0; o < OL_; o++) { acc0[o] = sB[o]; acc1[o] = sB[o]; }
#pragma unroll
        for (int i4 = 0; i4 < GL_ / 4; i4++) {
            float4 v0 = xp0[i4], v1 = xp1[i4];
            float xs0[4] = { v0.x, v0.y, v0.z, v0.w };
            float xs1[4] = { v1.x, v1.y, v1.z, v1.w };
#pragma unroll
            for (int c = 0; c < 4; c++) {
                const int i = i4 * 4 + c;
                const float a = xs0[c], b = xs1[c];
#pragma unroll
                for (int o4 = 0; o4 < 5; o4++) {
                    float4 w = *(const float4*)&sW[i * OL_ + o4 * 4];
                    acc0[o4*4+0] = fmaf(a, w.x, acc0[o4*4+0]);
                    acc0[o4*4+1] = fmaf(a, w.y, acc0[o4*4+1]);
                    acc0[o4*4+2] = fmaf(a, w.z, acc0[o4*4+2]);
                    acc0[o4*4+3] = fmaf(a, w.w, acc0[o4*4+3]);
                    acc1[o4*4+0] = fmaf(b, w.x, acc1[o4*4+0]);
                    acc1[o4*4+1] = fmaf(b, w.y, acc1[o4*4+1]);
                    acc1[o4*4+2] = fmaf(b, w.z, acc1[o4*4+2]);
                    acc1[o4*4+3] = fmaf(b, w.w, acc1[o4*4+3]);
                }
            }
        }
        float h0[OL_], h1[OL_];
#pragma unroll
        for (int o = 0; o < OL_; o++) {
            float t0 = ftanh(acc0[o]), t1 = ftanh(acc1[o]);
            h0[o] = t0; h1[o] = t1;
            sum[o] += t0 + t1;
            sq[o] = fmaf(t0, t0, sq[o]); sq[o] = fmaf(t1, t1, sq[o]);
        }
        float4* op0 = (float4*)(g_leaf_h + ((long)s * B_ + b0) * OL_);
        float4* op1 = (float4*)(g_leaf_h + ((long)s * B_ + b0 + 128) * OL_);
#pragma unroll
        for (int o4 = 0; o4 < 5; o4++) {
            op0[o4] = make_float4(h0[o4*4+0], h0[o4*4+1], h0[o4*4+2], h0[o4*4+3]);
            op1[o4] = make_float4(h1[o4*4+0], h1[o4*4+1], h1[o4*4+2], h1[o4*4+3]);
        }
    }

#pragma unroll
    for (int o = 0; o < OL_; o++) {
        for (int off = 16; off > 0; off >>= 1) {
            sum[o] += __shfl_down_sync(0xffffffffu, sum[o], off);
            sq[o]  += __shfl_down_sync(0xffffffffu, sq[o],  off);
        }
    }
    const int warp = tid >> 5, lane = tid & 31;
    if (lane == 0) {
#pragma unroll
        for (int o = 0; o < OL_; o++) { sRed[warp*40+o] = sum[o]; sRed[warp*40+20+o] = sq[o]; }
    }
    __syncthreads();
    if (tid < OL_) {
        float s1 = 0.f, s2 = 0.f;
        for (int w = 0; w < 4; w++) { s1 += sRed[w*40+tid]; s2 += sRed[w*40+20+tid]; }
        const float mean = s1 * (1.f / B_);
        const float var  = s2 * (1.f / B_) - mean * mean;
        const float a = gam[s * OL_ + tid] * rsqrtf(var + EPSF);
        g_leaf_ac[(s * OL_ + tid) * 2 + 0] = a;
        g_leaf_ac[(s * OL_ + tid) * 2 + 1] = bet[s * OL_ + tid] - mean * a;
    }
}

// ============================================================================
// Kernel 2: fold leaf BN (a,c) into mid weights/bias.
// W'[i][o] = a_i * W[i][o] (a=1 for gene rows); b'[o] = b[o] + sum_child c_i W[i][o]
// ============================================================================
__global__ __launch_bounds__(256) void k_prep_mid(
    const float* __restrict__ W_mid, const float* __restrict__ b_mid)
{
    const int m = blockIdx.x;
    const int tid = threadIdx.x;
    for (int idx = tid; idx < IM_ * OM_; idx += 256) {
        const int i = idx / OM_;
        float a = (i < GM_) ? 1.f : g_leaf_ac[(m * (C_ * OL_) + (i - GM_)) * 2 + 0];
        g_Wmid[m * IM_ * OM_ + idx] = a * W_mid[m * IM_ * OM_ + idx];
    }
    const int warp = tid >> 5, lane = tid & 31;
    for (int o = warp; o < OM_; o += 8) {
        float p = 0.f;
        for (int i = GM_ + lane; i < IM_; i += 32)
            p = fmaf(g_leaf_ac[(m * (C_ * OL_) + (i - GM_)) * 2 + 1],
                     W_mid[m * IM_ * OM_ + i * OM_ + o], p);
        for (int off = 16; off > 0; off >>= 1)
            p += __shfl_down_sync(0xffffffffu, p, off);
        if (lane == 0) g_bmid[m * OM_ + o] = b_mid[m * OM_ + o] + p;
    }
}

// ============================================================================
// Kernel 3: mid. grid(MC_=8 chunks, 32 mids), 128 thr, 2 batch rows/thread.
// Reads RAW leaf h (BN folded into weights). Writes raw mid h b-major.
// ============================================================================
__global__ __launch_bounds__(128) void k_mid(const float* __restrict__ x_mid)
{
    const int chunk = blockIdx.x;
    const int m = blockIdx.y;
    const int tid = threadIdx.x;
    const int b0 = chunk * 256 + tid;     // rows b0, b0+128

    __shared__ __align__(16) float sW[IM_ * OM_];
    __shared__ float sB[OM_];
    __shared__ float sRed[4 * 40];

    for (int i = tid; i < IM_ * OM_; i += 128) sW[i] = g_Wmid[m * IM_ * OM_ + i];
    if (tid < OM_) sB[tid] = g_bmid[m * OM_ + tid];
    __syncthreads();

    float acc0[OM_], acc1[OM_];
#pragma unroll
    for (int o = 0; o < OM_; o++) { acc0[o] = sB[o]; acc1[o] = sB[o]; }

    // genes (rows 0..63)
    const float4* xm0 = (const float4*)(x_mid + ((long)m * B_ + b0) * GM_);
    const float4* xm1 = (const float4*)(x_mid + ((long)m * B_ + b0 + 128) * GM_);
#pragma unroll 1
    for (int i4 = 0; i4 < GM_ / 4; i4++) {
        float4 v0 = xm0[i4], v1 = xm1[i4];
        float xs0[4] = { v0.x, v0.y, v0.z, v0.w };
        float xs1[4] = { v1.x, v1.y, v1.z, v1.w };
#pragma unroll
        for (int c = 0; c < 4; c++) {
            const int i = i4 * 4 + c;
            const float a = xs0[c], b = xs1[c];
#pragma unroll
            for (int o4 = 0; o4 < 5; o4++) {
                float4 w = *(const float4*)&sW[i * OM_ + o4 * 4];
                acc0[o4*4+0] = fmaf(a, w.x, acc0[o4*4+0]);
                acc0[o4*4+1] = fmaf(a, w.y, acc0[o4*4+1]);
                acc0[o4*4+2] = fmaf(a, w.z, acc0[o4*4+2]);
                acc0[o4*4+3] = fmaf(a, w.w, acc0[o4*4+3]);
                acc1[o4*4+0] = fmaf(b, w.x, acc1[o4*4+0]);
                acc1[o4*4+1] = fmaf(b, w.y, acc1[o4*4+1]);
                acc1[o4*4+2] = fmaf(b, w.z, acc1[o4*4+2]);
                acc1[o4*4+3] = fmaf(b, w.w, acc1[o4*4+3]);
            }
        }
    }
    // children (rows 64..383): raw leaf h
#pragma unroll 1
    for (int j = 0; j < C_; j++) {
        const float4* hp0 = (const float4*)(g_leaf_h + (((long)(m * C_ + j)) * B_ + b0) * OL_);
        const float4* hp1 = (const float4*)(g_leaf_h + (((long)(m * C_ + j)) * B_ + b0 + 128) * OL_);
        const int rbase = GM_ + j * OL_;
#pragma unroll
        for (int e4 = 0; e4 < 5; e4++) {
            float4 v0 = hp0[e4], v1 = hp1[e4];
            float xs0[4] = { v0.x, v0.y, v0.z, v0.w };
            float xs1[4] = { v1.x, v1.y, v1.z, v1.w };
#pragma unroll
            for (int c = 0; c < 4; c++) {
                const int i = rbase + e4 * 4 + c;
                const float a = xs0[c], b = xs1[c];
#pragma unroll
                for (int o4 = 0; o4 < 5; o4++) {
                    float4 w = *(const float4*)&sW[i * OM_ + o4 * 4];
                    acc0[o4*4+0] = fmaf(a, w.x, acc0[o4*4+0]);
                    acc0[o4*4+1] = fmaf(a, w.y, acc0[o4*4+1]);
                    acc0[o4*4+2] = fmaf(a, w.z, acc0[o4*4+2]);
                    acc0[o4*4+3] = fmaf(a, w.w, acc0[o4*4+3]);
                    acc1[o4*4+0] = fmaf(b, w.x, acc1[o4*4+0]);
                    acc1[o4*4+1] = fmaf(b, w.y, acc1[o4*4+1]);
                    acc1[o4*4+2] = fmaf(b, w.z, acc1[o4*4+2]);
                    acc1[o4*4+3] = fmaf(b, w.w, acc1[o4*4+3]);
                }
            }
        }
    }

    float sum[OM_], sq[OM_], h0[OM_], h1[OM_];
#pragma unroll
    for (int o = 0; o < OM_; o++) {
        float t0 = ftanh(acc0[o]), t1 = ftanh(acc1[o]);
        h0[o] = t0; h1[o] = t1;
        sum[o] = t0 + t1;
        sq[o] = fmaf(t0, t0, t1 * t1);
    }
    float4* op0 = (float4*)(g_mid_h + (long)b0 * (M_ * OM_) + m * OM_);
    float4* op1 = (float4*)(g_mid_h + (long)(b0 + 128) * (M_ * OM_) + m * OM_);
#pragma unroll
    for (int o4 = 0; o4 < 5; o4++) {
        op0[o4] = make_float4(h0[o4*4+0], h0[o4*4+1], h0[o4*4+2], h0[o4*4+3]);
        op1[o4] = make_float4(h1[o4*4+0], h1[o4*4+1], h1[o4*4+2], h1[o4*4+3]);
    }

#pragma unroll
    for (int o = 0; o < OM_; o++) {
        for (int off = 16; off > 0; off >>= 1) {
            sum[o] += __shfl_down_sync(0xffffffffu, sum[o], off);
            sq[o]  += __shfl_down_sync(0xffffffffu, sq[o],  off);
        }
    }
    const int warp = tid >> 5, lane = tid & 31;
    if (lane == 0) {
#pragma unroll
        for (int o = 0; o < OM_; o++) { sRed[warp*40+o] = sum[o]; sRed[warp*40+20+o] = sq[o]; }
    }
    __syncthreads();
    if (tid < OM_) {
        float s1 = 0.f, s2 = 0.f;
        for (int w = 0; w < 4; w++) { s1 += sRed[w*40+tid]; s2 += sRed[w*40+20+tid]; }
        g_mid_part[((m * MC_ + chunk) * OM_ + tid) * 2 + 0] = s1;
        g_mid_part[((m * MC_ + chunk) * OM_ + tid) * 2 + 1] = s2;
    }
}

// ============================================================================
// Kernel 4: finalize mid BN -> (a,c) per root-input index
// ============================================================================
__global__ void k_midac(const float* __restrict__ gam, const float* __restrict__ bet)
{
    const int t = threadIdx.x;  // 768 threads, 1 block
    if (t < GR_) {
        g_ac_root[t * 2 + 0] = 1.f;
        g_ac_root[t * 2 + 1] = 0.f;
    } else {
        const int idx = t - GR_;
        float s1 = 0.f, s2 = 0.f;
        const int mbase = (idx / OM_) * MC_ * OM_ + (idx % OM_);
#pragma unroll
        for (int ch = 0; ch < MC_; ch++) {
            s1 += g_mid_part[(mbase + ch * OM_) * 2 + 0];
            s2 += g_mid_part[(mbase + ch * OM_) * 2 + 1];
        }
        const float mean = s1 * (1.f / B_);
        const float var  = s2 * (1.f / B_) - mean * mean;
        const float a = gam[idx] * rsqrtf(var + EPSF);
        g_ac_root[t * 2 + 0] = a;
        g_ac_root[t * 2 + 1] = bet[idx] - mean * a;
    }
}

// ============================================================================
// Kernel 5: fold (a,c) into root weights/bias. grid=40 blocks (one per padded o)
// ============================================================================
__global__ __launch_bounds__(256) void k_prep_root(
    const float* __restrict__ W_root, const float* __restrict__ b_root)
{
    const int o = blockIdx.x;
    const int tid = threadIdx.x;
    float p = 0.f;
    for (int k = tid; k < IR_; k += 256) {
        const float a = g_ac_root[k * 2 + 0];
        const float c = g_ac_root[k * 2 + 1];
        const float w = (o < OR_) ? W_root[k * OR_ + o] : 0.f;
        g_Wroot[k * 40 + o] = a * w;
        p = fmaf(c, w, p);
    }
    for (int off = 16; off > 0; off >>= 1)
        p += __shfl_down_sync(0xffffffffu, p, off);
    __shared__ float r[8];
    if ((tid & 31) == 0) r[tid >> 5] = p;
    __syncthreads();
    if (tid == 0) {
        float s = (o < OR_) ? b_root[o] : 0.f;
        for (int w = 0; w < 8; w++) s += r[w];
        g_broot[o] = s;
    }
}

// ============================================================================
// Kernel 6: root GEMM K-split. grid(KC_=16, 8 bc), 256 thr, thread per b.
// ============================================================================
__global__ __launch_bounds__(256) void k_rootp(const float* __restrict__ x_root)
{
    const int kc = blockIdx.x;
    const int bc = blockIdx.y;
    const int tid = threadIdx.x;
    const int b = bc * 256 + tid;

    __shared__ __align__(16) float sW[48 * 40];
    for (int idx = tid; idx < 48 * 40; idx += 256)
        sW[idx] = g_Wroot[kc * 48 * 40 + idx];
    __syncthreads();

    float acc[40];
#pragma unroll
    for (int o = 0; o < 40; o++) acc[o] = 0.f;

    const float4* px = (const float4*)(x_root + (long)b * GR_);
    const float4* pm = (const float4*)(g_mid_h + (long)b * (M_ * OM_));

#pragma unroll 1
    for (int kl4 = 0; kl4 < 12; kl4++) {
        const int k0 = kc * 48 + kl4 * 4;
        const float4 v = (k0 < GR_) ? px[k0 >> 2] : pm[(k0 - GR_) >> 2];
        float xs[4] = { v.x, v.y, v.z, v.w };
#pragma unroll
        for (int c = 0; c < 4; c++) {
            const int kl = kl4 * 4 + c;
            const float xn = xs[c];
#pragma unroll
            for (int o4 = 0; o4 < 10; o4++) {
                float4 w = *(const float4*)&sW[kl * 40 + o4 * 4];
                acc[o4*4+0] = fmaf(xn, w.x, acc[o4*4+0]);
                acc[o4*4+1] = fmaf(xn, w.y, acc[o4*4+1]);
                acc[o4*4+2] = fmaf(xn, w.z, acc[o4*4+2]);
                acc[o4*4+3] = fmaf(xn, w.w, acc[o4*4+3]);
            }
        }
    }
    float4* op = (float4*)(g_root_part + ((long)kc * B_ + b) * 40);
#pragma unroll
    for (int o4 = 0; o4 < 10; o4++)
        op[o4] = make_float4(acc[o4*4+0], acc[o4*4+1], acc[o4*4+2], acc[o4*4+3]);
}

// ============================================================================
// Kernel 7: combine K-split partials + bias + tanh
// ============================================================================
__global__ __launch_bounds__(256) void k_rootcomb()
{
    const int e = blockIdx.x * 256 + threadIdx.x;   // 304*256 == 2048*38
    const int b = e / OR_, o = e % OR_;
    float s = g_broot[o];
#pragma unroll
    for (int kc = 0; kc < KC_; kc++)
        s += g_root_part[((long)kc * B_ + b) * 40 + o];
    g_root_h[e] = ftanh(s);
}

// ============================================================================
// Kernel 8: root BN stats
// ============================================================================
__global__ __launch_bounds__(256) void k_rootstats(
    const float* __restrict__ gam, const float* __restrict__ bet)
{
    const int o = blockIdx.x;
    const int tid = threadIdx.x;
    float s1 = 0.f, s2 = 0.f;
    for (int b = tid; b < B_; b += 256) {
        const float h = g_root_h[b * OR_ + o];
        s1 += h; s2 = fmaf(h, h, s2);
    }
    for (int off = 16; off > 0; off >>= 1) {
        s1 += __shfl_down_sync(0xffffffffu, s1, off);
        s2 += __shfl_down_sync(0xffffffffu, s2, off);
    }
    __shared__ float r1[8], r2[8];
    if ((tid & 31) == 0) { r1[tid >> 5] = s1; r2[tid >> 5] = s2; }
    __syncthreads();
    if (tid == 0) {
        float t1 = 0.f, t2 = 0.f;
        for (int w = 0; w < 8; w++) { t1 += r1[w]; t2 += r2[w]; }
        const float mean = t1 * (1.f / B_);
        const float var  = t2 * (1.f / B_) - mean * mean;
        const float a = gam[o] * rsqrtf(var + EPSF);
        g_root_ac[o * 2 + 0] = a;
        g_root_ac[o * 2 + 1] = bet[o] - mean * a;
    }
}

// ============================================================================
// Kernel 9: normalize root -> output
// ============================================================================
__global__ __launch_bounds__(256) void k_rootnorm(float* __restrict__ out)
{
    const int e = blockIdx.x * 256 + threadIdx.x;
    const int o = e % OR_;
    out[e] = fmaf(g_root_h[e], g_root_ac[o * 2 + 0], g_root_ac[o * 2 + 1]);
}

// ============================================================================
extern "C" void kernel_launch(void* const* d_in, const int* in_sizes, int n_in,
                              void* d_out, int out_size)
{
    const float* x_leaf = (const float*)d_in[0];
    const float* x_mid  = (const float*)d_in[1];
    const float* x_root = (const float*)d_in[2];
    const float* W_leaf = (const float*)d_in[3];
    const float* b_leaf = (const float*)d_in[4];
    const float* gleaf  = (const float*)d_in[5];
    const float* beleaf = (const float*)d_in[6];
    const float* W_mid  = (const float*)d_in[7];
    const float* b_mid  = (const float*)d_in[8];
    const float* gmid   = (const float*)d_in[9];
    const float* bemid  = (const float*)d_in[10];
    const float* W_root = (const float*)d_in[11];
    const float* b_root = (const float*)d_in[12];
    const float* groot  = (const float*)d_in[13];
    const float* beroot = (const float*)d_in[14];
    float* out = (float*)d_out;

    k_leaf<<<S_, 128>>>(x_leaf, W_leaf, b_leaf, gleaf, beleaf);
    k_prep_mid<<<M_, 256>>>(W_mid, b_mid);
    k_mid<<<dim3(MC_, M_), 128>>>(x_mid);
    k_midac<<<1, 768>>>(gmid, bemid);
    k_prep_root<<<40, 256>>>(W_root, b_root);
    k_rootp<<<dim3(KC_, 8), 256>>>(x_root);
    k_rootcomb<<<304, 256>>>();
    k_rootstats<<<OR_, 256>>>(groot, beroot);
    k_rootnorm<<<304, 256>>>(out);
}

// round 4
// speedup vs baseline: 1.9267x; 1.7868x over previous
#include <cuda_runtime.h>
#include <math.h>

// ---- problem dims ----
#define S_   512
#define B_   2048
#define GL_  32
#define OL_  20
#define M_   32
#define C_   16
#define GM_  64
#define OM_  20
#define GR_  128
#define OR_  38
#define IM_  384
#define IR_  768
#define EPSF 1e-5f
#define MC_  8        // mid batch chunks (256 rows each)
#define KC_  16       // root K chunks (48 rows each)

typedef unsigned long long ull;

// ---- scratch ----
__device__ float g_leaf_h[S_ * B_ * OL_];
__device__ float g_leaf_ac[S_ * OL_ * 2];
__device__ float g_Wmid[M_ * IM_ * OM_];
__device__ float g_bmid[M_ * OM_];
__device__ float g_mid_h[B_ * M_ * OM_];
__device__ float g_mid_part[M_ * MC_ * OM_ * 2];
__device__ float g_ac_root[IR_ * 2];
__device__ float g_Wroot[IR_ * 40];
__device__ float g_broot[40];
__device__ float g_root_part[KC_ * B_ * 40];
__device__ float g_root_h[B_ * OR_];
__device__ float g_root_ac[OR_ * 2];

// ---- packed f32x2 helpers ----
__device__ __forceinline__ ull pack2(float lo, float hi) {
    ull r; asm("mov.b64 %0, {%1, %2};" : "=l"(r) : "f"(lo), "f"(hi)); return r;
}
__device__ __forceinline__ ull dup2(float v) {
    ull r; asm("mov.b64 %0, {%1, %1};" : "=l"(r) : "f"(v)); return r;
}
__device__ __forceinline__ void unpack2(ull v, float& lo, float& hi) {
    asm("mov.b64 {%0, %1}, %2;" : "=f"(lo), "=f"(hi) : "l"(v));
}
__device__ __forceinline__ void fma2(ull& d, ull a, ull b) {
    asm("fma.rn.f32x2 %0, %1, %2, %3;" : "=l"(d) : "l"(a), "l"(b), "l"(d));
}
__device__ __forceinline__ ull add2(ull a, ull b) {
    ull r; asm("add.rn.f32x2 %0, %1, %2;" : "=l"(r) : "l"(a), "l"(b)); return r;
}

// fast tanh: 1 - 2/(exp(2x)+1), ~2e-7 abs error
__device__ __forceinline__ float ftanh(float x) {
    float e;
    asm("ex2.approx.f32 %0, %1;" : "=f"(e) : "f"(x * 2.885390081777927f));
    float r;
    asm("rcp.approx.f32 %0, %1;" : "=f"(r) : "f"(e + 1.0f));
    return fmaf(-2.f, r, 1.f);
}
__device__ __forceinline__ ull ftanh2(ull v) {
    float a, b; unpack2(v, a, b);
    return pack2(ftanh(a), ftanh(b));
}

// ============================================================================
// Kernel 1: leaf. One block/subsystem, 256 thr, 2 rows/thread/iter, 4 iters.
// 10 packed f32x2 output pairs per row (ALL 20 outputs).
// ============================================================================
__global__ __launch_bounds__(256) void k_leaf(
    const float* __restrict__ x_leaf, const float* __restrict__ W_leaf,
    const float* __restrict__ b_leaf, const float* __restrict__ gam,
    const float* __restrict__ bet)
{
    const int s = blockIdx.x;
    const int tid = threadIdx.x;
    __shared__ __align__(16) float sW[GL_ * OL_];
    __shared__ __align__(16) ull sBp[10];
    __shared__ float sRed[8 * 40];

    for (int i = tid; i < GL_ * OL_; i += 256) sW[i] = W_leaf[s * GL_ * OL_ + i];
    if (tid < 10)
        sBp[tid] = pack2(b_leaf[s * OL_ + tid * 2], b_leaf[s * OL_ + tid * 2 + 1]);
    __syncthreads();

    ull sum[10], sq[10];
#pragma unroll
    for (int p = 0; p < 10; p++) { sum[p] = 0ull; sq[p] = 0ull; }

#pragma unroll 1
    for (int it = 0; it < 4; it++) {
        const int r0 = it * 512 + tid;       // rows r0 and r0+256
        const float4* xp0 = (const float4*)(x_leaf + ((long)s * B_ + r0) * GL_);
        const float4* xp1 = (const float4*)(x_leaf + ((long)s * B_ + r0 + 256) * GL_);
        ull acc0[10], acc1[10];
#pragma unroll
        for (int p = 0; p < 10; p++) { acc0[p] = sBp[p]; acc1[p] = sBp[p]; }

#pragma unroll 2
        for (int i4 = 0; i4 < GL_ / 4; i4++) {
            float4 v0 = xp0[i4], v1 = xp1[i4];
            float xs0[4] = { v0.x, v0.y, v0.z, v0.w };
            float xs1[4] = { v1.x, v1.y, v1.z, v1.w };
#pragma unroll
            for (int c = 0; c < 4; c++) {
                const int i = i4 * 4 + c;
                const ull xa = dup2(xs0[c]);
                const ull xb = dup2(xs1[c]);
                const ulonglong2* wq = (const ulonglong2*)&sW[i * OL_];  // 5 x 16B
#pragma unroll
                for (int q = 0; q < 5; q++) {
                    ulonglong2 w2 = wq[q];
                    fma2(acc0[2*q+0], xa, w2.x); fma2(acc0[2*q+1], xa, w2.y);
                    fma2(acc1[2*q+0], xb, w2.x); fma2(acc1[2*q+1], xb, w2.y);
                }
            }
        }
        ull* op0 = (ull*)(g_leaf_h + ((long)s * B_ + r0) * OL_);
        ull* op1 = (ull*)(g_leaf_h + ((long)s * B_ + r0 + 256) * OL_);
#pragma unroll
        for (int p = 0; p < 10; p++) {
            ull h0 = ftanh2(acc0[p]);
            ull h1 = ftanh2(acc1[p]);
            sum[p] = add2(sum[p], add2(h0, h1));
            fma2(sq[p], h0, h0);
            fma2(sq[p], h1, h1);
            op0[p] = h0; op1[p] = h1;
        }
    }

    float s20[OL_], q20[OL_];
#pragma unroll
    for (int p = 0; p < 10; p++) {
        unpack2(sum[p], s20[2*p], s20[2*p+1]);
        unpack2(sq[p],  q20[2*p], q20[2*p+1]);
    }
#pragma unroll
    for (int o = 0; o < OL_; o++) {
        for (int off = 16; off > 0; off >>= 1) {
            s20[o] += __shfl_down_sync(0xffffffffu, s20[o], off);
            q20[o] += __shfl_down_sync(0xffffffffu, q20[o], off);
        }
    }
    const int warp = tid >> 5, lane = tid & 31;
    if (lane == 0) {
#pragma unroll
        for (int o = 0; o < OL_; o++) { sRed[warp*40+o] = s20[o]; sRed[warp*40+20+o] = q20[o]; }
    }
    __syncthreads();
    if (tid < OL_) {
        float s1 = 0.f, s2 = 0.f;
        for (int w = 0; w < 8; w++) { s1 += sRed[w*40+tid]; s2 += sRed[w*40+20+tid]; }
        const float mean = s1 * (1.f / B_);
        const float var  = s2 * (1.f / B_) - mean * mean;
        const float a = gam[s * OL_ + tid] * rsqrtf(var + EPSF);
        g_leaf_ac[(s * OL_ + tid) * 2 + 0] = a;
        g_leaf_ac[(s * OL_ + tid) * 2 + 1] = bet[s * OL_ + tid] - mean * a;
    }
}

// ============================================================================
// Kernel 2: fold leaf BN into mid weights/bias
// ============================================================================
__global__ __launch_bounds__(256) void k_prep_mid(
    const float* __restrict__ W_mid, const float* __restrict__ b_mid)
{
    const int m = blockIdx.x;
    const int tid = threadIdx.x;
    for (int idx = tid; idx < IM_ * OM_; idx += 256) {
        const int i = idx / OM_;
        float a = (i < GM_) ? 1.f : g_leaf_ac[(m * (C_ * OL_) + (i - GM_)) * 2 + 0];
        g_Wmid[m * IM_ * OM_ + idx] = a * W_mid[m * IM_ * OM_ + idx];
    }
    const int warp = tid >> 5, lane = tid & 31;
    for (int o = warp; o < OM_; o += 8) {
        float p = 0.f;
        for (int i = GM_ + lane; i < IM_; i += 32)
            p = fmaf(g_leaf_ac[(m * (C_ * OL_) + (i - GM_)) * 2 + 1],
                     W_mid[m * IM_ * OM_ + i * OM_ + o], p);
        for (int off = 16; off > 0; off >>= 1)
            p += __shfl_down_sync(0xffffffffu, p, off);
        if (lane == 0) g_bmid[m * OM_ + o] = b_mid[m * OM_ + o] + p;
    }
}

// ============================================================================
// Kernel 3: mid. grid(MC_=8, 32), 128 thr, 2 rows/thread, 10 packed pairs.
// ============================================================================
__global__ __launch_bounds__(128) void k_mid(const float* __restrict__ x_mid)
{
    const int chunk = blockIdx.x;
    const int m = blockIdx.y;
    const int tid = threadIdx.x;
    const int r0 = chunk * 256 + tid;      // rows r0, r0+128

    __shared__ __align__(16) float sW[IM_ * OM_];
    __shared__ __align__(16) ull sBp[10];
    __shared__ float sRed[4 * 40];

    for (int i = tid; i < IM_ * OM_; i += 128) sW[i] = g_Wmid[m * IM_ * OM_ + i];
    if (tid < 10)
        sBp[tid] = pack2(g_bmid[m * OM_ + tid * 2], g_bmid[m * OM_ + tid * 2 + 1]);
    __syncthreads();

    ull acc0[10], acc1[10];
#pragma unroll
    for (int p = 0; p < 10; p++) { acc0[p] = sBp[p]; acc1[p] = sBp[p]; }

    // genes (rows 0..63)
    const float4* xm0 = (const float4*)(x_mid + ((long)m * B_ + r0) * GM_);
    const float4* xm1 = (const float4*)(x_mid + ((long)m * B_ + r0 + 128) * GM_);
#pragma unroll 2
    for (int i4 = 0; i4 < GM_ / 4; i4++) {
        float4 v0 = xm0[i4], v1 = xm1[i4];
        float xs0[4] = { v0.x, v0.y, v0.z, v0.w };
        float xs1[4] = { v1.x, v1.y, v1.z, v1.w };
#pragma unroll
        for (int c = 0; c < 4; c++) {
            const int i = i4 * 4 + c;
            const ull xa = dup2(xs0[c]);
            const ull xb = dup2(xs1[c]);
            const ulonglong2* wq = (const ulonglong2*)&sW[i * OM_];
#pragma unroll
            for (int q = 0; q < 5; q++) {
                ulonglong2 w2 = wq[q];
                fma2(acc0[2*q+0], xa, w2.x); fma2(acc0[2*q+1], xa, w2.y);
                fma2(acc1[2*q+0], xb, w2.x); fma2(acc1[2*q+1], xb, w2.y);
            }
        }
    }
    // children (rows 64..383)
#pragma unroll 1
    for (int j = 0; j < C_; j++) {
        const float4* hp0 = (const float4*)(g_leaf_h + (((long)(m * C_ + j)) * B_ + r0) * OL_);
        const float4* hp1 = (const float4*)(g_leaf_h + (((long)(m * C_ + j)) * B_ + r0 + 128) * OL_);
        const int rbase = GM_ + j * OL_;
#pragma unroll
        for (int e4 = 0; e4 < 5; e4++) {
            float4 v0 = hp0[e4], v1 = hp1[e4];
            float xs0[4] = { v0.x, v0.y, v0.z, v0.w };
            float xs1[4] = { v1.x, v1.y, v1.z, v1.w };
#pragma unroll
            for (int c = 0; c < 4; c++) {
                const int i = rbase + e4 * 4 + c;
                const ull xa = dup2(xs0[c]);
                const ull xb = dup2(xs1[c]);
                const ulonglong2* wq = (const ulonglong2*)&sW[i * OM_];
#pragma unroll
                for (int q = 0; q < 5; q++) {
                    ulonglong2 w2 = wq[q];
                    fma2(acc0[2*q+0], xa, w2.x); fma2(acc0[2*q+1], xa, w2.y);
                    fma2(acc1[2*q+0], xb, w2.x); fma2(acc1[2*q+1], xb, w2.y);
                }
            }
        }
    }

    ull sum[10], sq[10];
    ull* op0 = (ull*)(g_mid_h + (long)r0 * (M_ * OM_) + m * OM_);
    ull* op1 = (ull*)(g_mid_h + (long)(r0 + 128) * (M_ * OM_) + m * OM_);
#pragma unroll
    for (int p = 0; p < 10; p++) {
        ull h0 = ftanh2(acc0[p]);
        ull h1 = ftanh2(acc1[p]);
        sum[p] = add2(h0, h1);
        sq[p] = 0ull;
        fma2(sq[p], h0, h0);
        fma2(sq[p], h1, h1);
        op0[p] = h0; op1[p] = h1;
    }

    float s20[OM_], q20[OM_];
#pragma unroll
    for (int p = 0; p < 10; p++) {
        unpack2(sum[p], s20[2*p], s20[2*p+1]);
        unpack2(sq[p],  q20[2*p], q20[2*p+1]);
    }
#pragma unroll
    for (int o = 0; o < OM_; o++) {
        for (int off = 16; off > 0; off >>= 1) {
            s20[o] += __shfl_down_sync(0xffffffffu, s20[o], off);
            q20[o] += __shfl_down_sync(0xffffffffu, q20[o], off);
        }
    }
    const int warp = tid >> 5, lane = tid & 31;
    if (lane == 0) {
#pragma unroll
        for (int o = 0; o < OM_; o++) { sRed[warp*40+o] = s20[o]; sRed[warp*40+20+o] = q20[o]; }
    }
    __syncthreads();
    if (tid < OM_) {
        float s1 = 0.f, s2 = 0.f;
        for (int w = 0; w < 4; w++) { s1 += sRed[w*40+tid]; s2 += sRed[w*40+20+tid]; }
        g_mid_part[((m * MC_ + chunk) * OM_ + tid) * 2 + 0] = s1;
        g_mid_part[((m * MC_ + chunk) * OM_ + tid) * 2 + 1] = s2;
    }
}

// ============================================================================
// Kernel 4: finalize mid BN -> (a,c) per root-input index
// ============================================================================
__global__ void k_midac(const float* __restrict__ gam, const float* __restrict__ bet)
{
    const int t = threadIdx.x;  // 768 threads
    if (t < GR_) {
        g_ac_root[t * 2 + 0] = 1.f;
        g_ac_root[t * 2 + 1] = 0.f;
    } else {
        const int idx = t - GR_;
        float s1 = 0.f, s2 = 0.f;
        const int mbase = (idx / OM_) * MC_ * OM_ + (idx % OM_);
#pragma unroll
        for (int ch = 0; ch < MC_; ch++) {
            s1 += g_mid_part[(mbase + ch * OM_) * 2 + 0];
            s2 += g_mid_part[(mbase + ch * OM_) * 2 + 1];
        }
        const float mean = s1 * (1.f / B_);
        const float var  = s2 * (1.f / B_) - mean * mean;
        const float a = gam[idx] * rsqrtf(var + EPSF);
        g_ac_root[t * 2 + 0] = a;
        g_ac_root[t * 2 + 1] = bet[idx] - mean * a;
    }
}

// ============================================================================
// Kernel 5: fold (a,c) into root weights/bias
// ============================================================================
__global__ __launch_bounds__(256) void k_prep_root(
    const float* __restrict__ W_root, const float* __restrict__ b_root)
{
    const int o = blockIdx.x;
    const int tid = threadIdx.x;
    float p = 0.f;
    for (int k = tid; k < IR_; k += 256) {
        const float a = g_ac_root[k * 2 + 0];
        const float c = g_ac_root[k * 2 + 1];
        const float w = (o < OR_) ? W_root[k * OR_ + o] : 0.f;
        g_Wroot[k * 40 + o] = a * w;
        p = fmaf(c, w, p);
    }
    for (int off = 16; off > 0; off >>= 1)
        p += __shfl_down_sync(0xffffffffu, p, off);
    __shared__ float r[8];
    if ((tid & 31) == 0) r[tid >> 5] = p;
    __syncthreads();
    if (tid == 0) {
        float s = (o < OR_) ? b_root[o] : 0.f;
        for (int w = 0; w < 8; w++) s += r[w];
        g_broot[o] = s;
    }
}

// ============================================================================
// Kernel 6: root GEMM K-split. grid(16, 16), 128 thr, packed outputs.
// ============================================================================
__global__ __launch_bounds__(128) void k_rootp(const float* __restrict__ x_root)
{
    const int kc = blockIdx.x;
    const int bc = blockIdx.y;
    const int tid = threadIdx.x;
    const int b = bc * 128 + tid;

    __shared__ __align__(16) float sW[48 * 40];
    for (int idx = tid; idx < 48 * 40; idx += 128)
        sW[idx] = g_Wroot[kc * 48 * 40 + idx];
    __syncthreads();

    ull acc[20];
#pragma unroll
    for (int p = 0; p < 20; p++) acc[p] = 0ull;

    const float4* px = (const float4*)(x_root + (long)b * GR_);
    const float4* pm = (const float4*)(g_mid_h + (long)b * (M_ * OM_));

#pragma unroll 1
    for (int kl4 = 0; kl4 < 12; kl4++) {
        const int k0 = kc * 48 + kl4 * 4;
        const float4 v = (k0 < GR_) ? px[k0 >> 2] : pm[(k0 - GR_) >> 2];
        float xs[4] = { v.x, v.y, v.z, v.w };
#pragma unroll
        for (int c = 0; c < 4; c++) {
            const int kl = kl4 * 4 + c;
            const ull xd = dup2(xs[c]);
            const ulonglong2* wp = (const ulonglong2*)&sW[kl * 40];
#pragma unroll
            for (int q = 0; q < 10; q++) {
                ulonglong2 w2 = wp[q];
                fma2(acc[2*q+0], xd, w2.x);
                fma2(acc[2*q+1], xd, w2.y);
            }
        }
    }
    ull* op = (ull*)(g_root_part + ((long)kc * B_ + b) * 40);
#pragma unroll
    for (int p = 0; p < 20; p++) op[p] = acc[p];
}

// ============================================================================
// Kernel 7: combine partials + bias + tanh
// ============================================================================
__global__ __launch_bounds__(256) void k_rootcomb()
{
    const int e = blockIdx.x * 256 + threadIdx.x;   // 304*256 == 2048*38
    const int b = e / OR_, o = e % OR_;
    float s = g_broot[o];
#pragma unroll
    for (int kc = 0; kc < KC_; kc++)
        s += g_root_part[((long)kc * B_ + b) * 40 + o];
    g_root_h[e] = ftanh(s);
}

// ============================================================================
// Kernel 8: root BN stats
// ============================================================================
__global__ __launch_bounds__(256) void k_rootstats(
    const float* __restrict__ gam, const float* __restrict__ bet)
{
    const int o = blockIdx.x;
    const int tid = threadIdx.x;
    float s1 = 0.f, s2 = 0.f;
    for (int b = tid; b < B_; b += 256) {
        const float h = g_root_h[b * OR_ + o];
        s1 += h; s2 = fmaf(h, h, s2);
    }
    for (int off = 16; off > 0; off >>= 1) {
        s1 += __shfl_down_sync(0xffffffffu, s1, off);
        s2 += __shfl_down_sync(0xffffffffu, s2, off);
    }
    __shared__ float r1[8], r2[8];
    if ((tid & 31) == 0) { r1[tid >> 5] = s1; r2[tid >> 5] = s2; }
    __syncthreads();
    if (tid == 0) {
        float t1 = 0.f, t2 = 0.f;
        for (int w = 0; w < 8; w++) { t1 += r1[w]; t2 += r2[w]; }
        const float mean = t1 * (1.f / B_);
        const float var  = t2 * (1.f / B_) - mean * mean;
        const float a = gam[o] * rsqrtf(var + EPSF);
        g_root_ac[o * 2 + 0] = a;
        g_root_ac[o * 2 + 1] = bet[o] - mean * a;
    }
}

// ============================================================================
// Kernel 9: normalize root -> output
// ============================================================================
__global__ __launch_bounds__(256) void k_rootnorm(float* __restrict__ out)
{
    const int e = blockIdx.x * 256 + threadIdx.x;
    const int o = e % OR_;
    out[e] = fmaf(g_root_h[e], g_root_ac[o * 2 + 0], g_root_ac[o * 2 + 1]);
}

// ============================================================================
extern "C" void kernel_launch(void* const* d_in, const int* in_sizes, int n_in,
                              void* d_out, int out_size)
{
    const float* x_leaf = (const float*)d_in[0];
    const float* x_mid  = (const float*)d_in[1];
    const float* x_root = (const float*)d_in[2];
    const float* W_leaf = (const float*)d_in[3];
    const float* b_leaf = (const float*)d_in[4];
    const float* gleaf  = (const float*)d_in[5];
    const float* beleaf = (const float*)d_in[6];
    const float* W_mid  = (const float*)d_in[7];
    const float* b_mid  = (const float*)d_in[8];
    const float* gmid   = (const float*)d_in[9];
    const float* bemid  = (const float*)d_in[10];
    const float* W_root = (const float*)d_in[11];
    const float* b_root = (const float*)d_in[12];
    const float* groot  = (const float*)d_in[13];
    const float* beroot = (const float*)d_in[14];
    float* out = (float*)d_out;

    k_leaf<<<S_, 256>>>(x_leaf, W_leaf, b_leaf, gleaf, beleaf);
    k_prep_mid<<<M_, 256>>>(W_mid, b_mid);
    k_mid<<<dim3(MC_, M_), 128>>>(x_mid);
    k_midac<<<1, 768>>>(gmid, bemid);
    k_prep_root<<<40, 256>>>(W_root, b_root);
    k_rootp<<<dim3(KC_, 16), 128>>>(x_root);
    k_rootcomb<<<304, 256>>>();
    k_rootstats<<<OR_, 256>>>(groot, beroot);
    k_rootnorm<<<304, 256>>>(out);
}

// round 8
// speedup vs baseline: 2.2053x; 1.1446x over previous
#include <cuda_runtime.h>
#include <math.h>

// ---- problem dims ----
#define S_   512
#define B_   2048
#define GL_  32
#define OL_  20
#define M_   32
#define C_   16
#define GM_  64
#define OM_  20
#define GR_  128
#define OR_  38
#define IM_  384
#define IR_  768
#define EPSF 1e-5f
#define MC_  8        // mid batch chunks (256 rows each)
#define PX_  258      // leaf x smem col-major pad (even -> 8B-aligned LDS.64)

typedef unsigned long long ull;

// ---- scratch ----
// TRANSPOSED intermediates: [feature][batch] for coalesced consumer reads.
__device__ float g_leaf_h[S_ * OL_ * B_];        // [s*20+o][b]
__device__ float g_leaf_part[S_ * 2 * 40];       // [(s*2+chunk)][sum20|sq20]
__device__ float g_Wmid[M_ * IM_ * OM_];
__device__ float g_bmid[M_ * OM_];
__device__ float g_mid_h[M_ * OM_ * B_];         // [m*20+o][b]
__device__ float g_mid_part[M_ * MC_ * OM_ * 2];
__device__ float g_root_part[17 * 40 * B_];      // [kc][oo][b], chunk 16 = genes
// ---- packed f32x2 helpers ----
__device__ __forceinline__ ull pack2(float lo, float hi) {
    ull r; asm("mov.b64 %0, {%1, %2};" : "=l"(r) : "f"(lo), "f"(hi)); return r;
}
__device__ __forceinline__ ull dup2(float v) {
    ull r; asm("mov.b64 %0, {%1, %1};" : "=l"(r) : "f"(v)); return r;
}
__device__ __forceinline__ void unpack2(ull v, float& lo, float& hi) {
    asm("mov.b64 {%0, %1}, %2;" : "=f"(lo), "=f"(hi) : "l"(v));
}
__device__ __forceinline__ void fma2(ull& d, ull a, ull b) {
    asm("fma.rn.f32x2 %0, %1, %2, %3;" : "=l"(d) : "l"(a), "l"(b), "l"(d));
}
__device__ __forceinline__ ull add2(ull a, ull b) {
    ull r; asm("add.rn.f32x2 %0, %1, %2;" : "=l"(r) : "l"(a), "l"(b)); return r;
}

// fast tanh: 1 - 2/(exp(2x)+1), ~2e-7 abs error
__device__ __forceinline__ float ftanh(float x) {
    float e;
    asm("ex2.approx.f32 %0, %1;" : "=f"(e) : "f"(x * 2.885390081777927f));
    float r;
    asm("rcp.approx.f32 %0, %1;" : "=f"(r) : "f"(e + 1.0f));
    return fmaf(-2.f, r, 1.f);
}
__device__ __forceinline__ ull ftanh2(ull v) {
    float a, b; unpack2(v, a, b);
    return pack2(ftanh(a), ftanh(b));
}

// ============================================================================
// Kernel 1: leaf. grid(2, 512): chunk c (1024 rows) x subsystem s. 128 thr,
// 2 adjacent rows/thread, 4 stages of 256 rows staged via col-major smem.
// Writes g_leaf_h TRANSPOSED [s*20+o][b] and partial stats.
// ============================================================================
__global__ __launch_bounds__(128) void k_leaf(
    const float* __restrict__ x_leaf, const float* __restrict__ W_leaf,
    const float* __restrict__ b_leaf)
{
    const int c = blockIdx.x;
    const int s = blockIdx.y;
    const int tid = threadIdx.x;
    __shared__ __align__(16) float sW[GL_ * OL_];
    __shared__ __align__(16) ull sBp[10];
    __shared__ __align__(16) float sX[GL_ * PX_];   // col-major [i][row]
    __shared__ float sRed[4 * 40];

    for (int i = tid; i < GL_ * OL_; i += 128) sW[i] = W_leaf[s * GL_ * OL_ + i];
    if (tid < 10)
        sBp[tid] = pack2(b_leaf[s * OL_ + tid * 2], b_leaf[s * OL_ + tid * 2 + 1]);

    ull sum[10], sq[10];
#pragma unroll
    for (int p = 0; p < 10; p++) { sum[p] = 0ull; sq[p] = 0ull; }

#pragma unroll 1
    for (int st = 0; st < 4; st++) {
        const int R = c * 1024 + st * 256;          // stage base row
        __syncthreads();
        // stage 256 rows x 32 floats, coalesced -> col-major smem
        const float4* gx = (const float4*)(x_leaf + ((long)s * B_ + R) * GL_);
#pragma unroll
        for (int k = 0; k < 16; k++) {
            const int f4 = tid + k * 128;           // 2048 float4 total
            const int bl = f4 >> 3;                 // row 0..255
            const int i0 = (f4 & 7) * 4;            // col 0,4,..28
            float4 v = gx[f4];
            sX[(i0 + 0) * PX_ + bl] = v.x;
            sX[(i0 + 1) * PX_ + bl] = v.y;
            sX[(i0 + 2) * PX_ + bl] = v.z;
            sX[(i0 + 3) * PX_ + bl] = v.w;
        }
        __syncthreads();

        const int bl = 2 * tid;                     // local rows bl, bl+1
        ull acc0[10], acc1[10];
#pragma unroll
        for (int p = 0; p < 10; p++) { acc0[p] = sBp[p]; acc1[p] = sBp[p]; }

#pragma unroll 4
        for (int i = 0; i < GL_; i++) {
            float2 xv = *(const float2*)&sX[i * PX_ + bl];   // conflict-free
            const ull xa = dup2(xv.x);
            const ull xb = dup2(xv.y);
            const ulonglong2* wq = (const ulonglong2*)&sW[i * OL_];
#pragma unroll
            for (int q = 0; q < 5; q++) {
                ulonglong2 w2 = wq[q];
                fma2(acc0[2*q+0], xa, w2.x); fma2(acc0[2*q+1], xa, w2.y);
                fma2(acc1[2*q+0], xb, w2.x); fma2(acc1[2*q+1], xb, w2.y);
            }
        }
        // tanh, stats, transposed store
        const long bg = (long)R + bl;               // global batch index
#pragma unroll
        for (int p = 0; p < 10; p++) {
            ull h0 = ftanh2(acc0[p]);               // outputs (2p,2p+1) row bl
            ull h1 = ftanh2(acc1[p]);               // row bl+1
            sum[p] = add2(sum[p], add2(h0, h1));
            fma2(sq[p], h0, h0);
            fma2(sq[p], h1, h1);
            float a0, a1, b0, b1;
            unpack2(h0, a0, a1); unpack2(h1, b0, b1);
            *(ull*)&g_leaf_h[((long)s * OL_ + 2*p+0) * B_ + bg] = pack2(a0, b0);
            *(ull*)&g_leaf_h[((long)s * OL_ + 2*p+1) * B_ + bg] = pack2(a1, b1);
        }
    }

    float s20[OL_], q20[OL_];
#pragma unroll
    for (int p = 0; p < 10; p++) {
        unpack2(sum[p], s20[2*p], s20[2*p+1]);
        unpack2(sq[p],  q20[2*p], q20[2*p+1]);
    }
#pragma unroll
    for (int o = 0; o < OL_; o++) {
        for (int off = 16; off > 0; off >>= 1) {
            s20[o] += __shfl_down_sync(0xffffffffu, s20[o], off);
            q20[o] += __shfl_down_sync(0xffffffffu, q20[o], off);
        }
    }
    const int warp = tid >> 5, lane = tid & 31;
    if (lane == 0) {
#pragma unroll
        for (int o = 0; o < OL_; o++) { sRed[warp*40+o] = s20[o]; sRed[warp*40+20+o] = q20[o]; }
    }
    __syncthreads();
    if (tid < OL_) {
        float s1 = 0.f, s2 = 0.f;
        for (int w = 0; w < 4; w++) { s1 += sRed[w*40+tid]; s2 += sRed[w*40+20+tid]; }
        g_leaf_part[(s * 2 + c) * 40 + tid]      = s1;
        g_leaf_part[(s * 2 + c) * 40 + 20 + tid] = s2;
    }
}

// ============================================================================
// Kernel 2: finalize leaf BN + fold into mid weights/bias. grid=32 (per m).
// ============================================================================
__global__ __launch_bounds__(256) void k_prep_mid(
    const float* __restrict__ W_mid, const float* __restrict__ b_mid,
    const float* __restrict__ gam, const float* __restrict__ bet)
{
    const int m = blockIdx.x;
    const int tid = threadIdx.x;
    __shared__ float sA[C_ * OL_], sC[C_ * OL_];

    for (int idx = tid; idx < C_ * OL_; idx += 256) {   // grid-stride (320 > 256)
        const int s = m * C_ + idx / OL_;
        const int o = idx % OL_;
        const int base = (s * 2) * 40 + o;
        const float s1 = g_leaf_part[base] + g_leaf_part[base + 40];
        const float s2 = g_leaf_part[base + 20] + g_leaf_part[base + 60];
        const float mean = s1 * (1.f / B_);
        const float var  = s2 * (1.f / B_) - mean * mean;
        const float a = gam[s * OL_ + o] * rsqrtf(var + EPSF);
        sA[idx] = a;
        sC[idx] = bet[s * OL_ + o] - mean * a;
    }
    __syncthreads();

    for (int idx = tid; idx < IM_ * OM_; idx += 256) {
        const int i = idx / OM_;
        float a = (i < GM_) ? 1.f : sA[i - GM_];
        g_Wmid[m * IM_ * OM_ + idx] = a * W_mid[m * IM_ * OM_ + idx];
    }
    const int warp = tid >> 5, lane = tid & 31;
    for (int o = warp; o < OM_; o += 8) {
        float p = 0.f;
        for (int i = GM_ + lane; i < IM_; i += 32)
            p = fmaf(sC[i - GM_], W_mid[m * IM_ * OM_ + i * OM_ + o], p);
        for (int off = 16; off > 0; off >>= 1)
            p += __shfl_down_sync(0xffffffffu, p, off);
        if (lane == 0) g_bmid[m * OM_ + o] = b_mid[m * OM_ + o] + p;
    }
}

// ============================================================================
// Kernel 3: mid. grid(MC_=8, 32), 128 thr, 2 ADJACENT rows/thread (b=2t).
// Children read COALESCED from transposed g_leaf_h (LDG.64 row-pairs).
// Writes g_mid_h TRANSPOSED [m*20+o][b] + partial stats.
// ============================================================================
__global__ __launch_bounds__(128) void k_mid(const float* __restrict__ x_mid)
{
    const int chunk = blockIdx.x;
    const int m = blockIdx.y;
    const int tid = threadIdx.x;
    const int b0 = chunk * 256 + 2 * tid;           // rows b0, b0+1

    __shared__ __align__(16) float sW[IM_ * OM_];
    __shared__ __align__(16) ull sBp[10];
    __shared__ float sRed[4 * 40];

    for (int i = tid; i < IM_ * OM_; i += 128) sW[i] = g_Wmid[m * IM_ * OM_ + i];
    if (tid < 10)
        sBp[tid] = pack2(g_bmid[m * OM_ + tid * 2], g_bmid[m * OM_ + tid * 2 + 1]);
    __syncthreads();

    ull acc0[10], acc1[10];
#pragma unroll
    for (int p = 0; p < 10; p++) { acc0[p] = sBp[p]; acc1[p] = sBp[p]; }

    // genes (rows 0..63): direct loads (2 adjacent rows, 17% of K)
    {
        const float4* xm0 = (const float4*)(x_mid + ((long)m * B_ + b0) * GM_);
        const float4* xm1 = (const float4*)(x_mid + ((long)m * B_ + b0 + 1) * GM_);
#pragma unroll 2
        for (int i4 = 0; i4 < GM_ / 4; i4++) {
            float4 v0 = xm0[i4], v1 = xm1[i4];
            float xs0[4] = { v0.x, v0.y, v0.z, v0.w };
            float xs1[4] = { v1.x, v1.y, v1.z, v1.w };
#pragma unroll
            for (int cc = 0; cc < 4; cc++) {
                const int i = i4 * 4 + cc;
                const ull xa = dup2(xs0[cc]);
                const ull xb = dup2(xs1[cc]);
                const ulonglong2* wq = (const ulonglong2*)&sW[i * OM_];
#pragma unroll
                for (int q = 0; q < 5; q++) {
                    ulonglong2 w2 = wq[q];
                    fma2(acc0[2*q+0], xa, w2.x); fma2(acc0[2*q+1], xa, w2.y);
                    fma2(acc1[2*q+0], xb, w2.x); fma2(acc1[2*q+1], xb, w2.y);
                }
            }
        }
    }
    // children (rows 64..383): coalesced LDG.64 from transposed g_leaf_h
#pragma unroll 1
    for (int j = 0; j < C_; j++) {
        const long fbase = ((long)(m * C_ + j)) * OL_;   // feature row base
        float2 xp[OL_];
#pragma unroll
        for (int e = 0; e < OL_; e++)
            xp[e] = *(const float2*)&g_leaf_h[(fbase + e) * B_ + b0];
        const int rbase = GM_ + j * OL_;
#pragma unroll
        for (int e = 0; e < OL_; e++) {
            const ull xa = dup2(xp[e].x);
            const ull xb = dup2(xp[e].y);
            const ulonglong2* wq = (const ulonglong2*)&sW[(rbase + e) * OM_];
#pragma unroll
            for (int q = 0; q < 5; q++) {
                ulonglong2 w2 = wq[q];
                fma2(acc0[2*q+0], xa, w2.x); fma2(acc0[2*q+1], xa, w2.y);
                fma2(acc1[2*q+0], xb, w2.x); fma2(acc1[2*q+1], xb, w2.y);
            }
        }
    }

    ull sum[10], sq[10];
#pragma unroll
    for (int p = 0; p < 10; p++) {
        ull h0 = ftanh2(acc0[p]);
        ull h1 = ftanh2(acc1[p]);
        sum[p] = add2(h0, h1);
        sq[p] = 0ull;
        fma2(sq[p], h0, h0);
        fma2(sq[p], h1, h1);
        float a0, a1, c0, c1;
        unpack2(h0, a0, a1); unpack2(h1, c0, c1);
        *(ull*)&g_mid_h[((long)m * OM_ + 2*p+0) * B_ + b0] = pack2(a0, c0);
        *(ull*)&g_mid_h[((long)m * OM_ + 2*p+1) * B_ + b0] = pack2(a1, c1);
    }

    float s20[OM_], q20[OM_];
#pragma unroll
    for (int p = 0; p < 10; p++) {
        unpack2(sum[p], s20[2*p], s20[2*p+1]);
        unpack2(sq[p],  q20[2*p], q20[2*p+1]);
    }
#pragma unroll
    for (int o = 0; o < OM_; o++) {
        for (int off = 16; off > 0; off >>= 1) {
            s20[o] += __shfl_down_sync(0xffffffffu, s20[o], off);
            q20[o] += __shfl_down_sync(0xffffffffu, q20[o], off);
        }
    }
    const int warp = tid >> 5, lane = tid & 31;
    if (lane == 0) {
#pragma unroll
        for (int o = 0; o < OM_; o++) { sRed[warp*40+o] = s20[o]; sRed[warp*40+20+o] = q20[o]; }
    }
    __syncthreads();
    if (tid < OM_) {
        float s1 = 0.f, s2 = 0.f;
        for (int w = 0; w < 4; w++) { s1 += sRed[w*40+tid]; s2 += sRed[w*40+20+tid]; }
        g_mid_part[((m * MC_ + chunk) * OM_ + tid) * 2 + 0] = s1;
        g_mid_part[((m * MC_ + chunk) * OM_ + tid) * 2 + 1] = s2;
    }
}

// ============================================================================
// Kernel 4: root child partials. grid(16 kc, 16 bc), 128 thr, thread per b.
// Computes mid (a,c) INLINE per block; reads g_mid_h coalesced; writes
// partials transposed [kc][oo][b].
// ============================================================================
__global__ __launch_bounds__(128) void k_rootp(
    const float* __restrict__ W_root,
    const float* __restrict__ gam, const float* __restrict__ bet)
{
    const int kc = blockIdx.x;
    const int bc = blockIdx.y;
    const int tid = threadIdx.x;
    const int b = bc * 128 + tid;

    __shared__ __align__(16) float sW[40 * 40];
    __shared__ float sA[40], sC[40];

    if (tid < 40) {                                   // inline BN finalize
        const int g = kc * 40 + tid;                  // child idx 0..639
        const int mm = g / OM_, o = g % OM_;
        float s1 = 0.f, s2 = 0.f;
#pragma unroll
        for (int ch = 0; ch < MC_; ch++) {
            s1 += g_mid_part[((mm * MC_ + ch) * OM_ + o) * 2 + 0];
            s2 += g_mid_part[((mm * MC_ + ch) * OM_ + o) * 2 + 1];
        }
        const float mean = s1 * (1.f / B_);
        const float var  = s2 * (1.f / B_) - mean * mean;
        const float a = gam[g] * rsqrtf(var + EPSF);
        sA[tid] = a;
        sC[tid] = bet[g] - mean * a;
    }
    for (int idx = tid; idx < 40 * 40; idx += 128) {
        const int kk = idx / 40, oo = idx % 40;
        sW[idx] = (oo < OR_) ? W_root[(GR_ + kc * 40 + kk) * OR_ + oo] : 0.f;
    }
    __syncthreads();

    float xn[40];
#pragma unroll
    for (int kk = 0; kk < 40; kk++) {
        const float x = g_mid_h[((long)(kc * 40 + kk)) * B_ + b];   // coalesced
        xn[kk] = fmaf(x, sA[kk], sC[kk]);
    }
    ull acc[20];
#pragma unroll
    for (int p = 0; p < 20; p++) acc[p] = 0ull;
#pragma unroll 4
    for (int kk = 0; kk < 40; kk++) {
        const ull xd = dup2(xn[kk]);
        const ulonglong2* wq = (const ulonglong2*)&sW[kk * 40];
#pragma unroll
        for (int q = 0; q < 10; q++) {
            ulonglong2 w2 = wq[q];
            fma2(acc[2*q+0], xd, w2.x);
            fma2(acc[2*q+1], xd, w2.y);
        }
    }
#pragma unroll
    for (int p = 0; p < 20; p++) {
        float lo, hi; unpack2(acc[p], lo, hi);
        g_root_part[((long)(kc * 40 + 2*p+0)) * B_ + b] = lo;       // coalesced
        g_root_part[((long)(kc * 40 + 2*p+1)) * B_ + b] = hi;
    }
}

// ============================================================================
// Kernel 5: root gene partials (k=0..127). grid 16, 128 thr, thread per b.
// ============================================================================
__global__ __launch_bounds__(128) void k_rootgene(
    const float* __restrict__ x_root, const float* __restrict__ W_root)
{
    const int tid = threadIdx.x;
    const int b = blockIdx.x * 128 + tid;

    __shared__ __align__(16) float sW[GR_ * 40];
    for (int idx = tid; idx < GR_ * 40; idx += 128) {
        const int kk = idx / 40, oo = idx % 40;
        sW[idx] = (oo < OR_) ? W_root[kk * OR_ + oo] : 0.f;
    }
    __syncthreads();

    ull acc[20];
#pragma unroll
    for (int p = 0; p < 20; p++) acc[p] = 0ull;

    const float4* px = (const float4*)(x_root + (long)b * GR_);
#pragma unroll 1
    for (int k4 = 0; k4 < GR_ / 4; k4++) {
        float4 v = px[k4];
        float xs[4] = { v.x, v.y, v.z, v.w };
#pragma unroll
        for (int cc = 0; cc < 4; cc++) {
            const ull xd = dup2(xs[cc]);
            const ulonglong2* wq = (const ulonglong2*)&sW[(k4 * 4 + cc) * 40];
#pragma unroll
            for (int q = 0; q < 10; q++) {
                ulonglong2 w2 = wq[q];
                fma2(acc[2*q+0], xd, w2.x);
                fma2(acc[2*q+1], xd, w2.y);
            }
        }
    }
#pragma unroll
    for (int p = 0; p < 20; p++) {
        float lo, hi; unpack2(acc[p], lo, hi);
        g_root_part[((long)(16 * 40 + 2*p+0)) * B_ + b] = lo;
        g_root_part[((long)(16 * 40 + 2*p+1)) * B_ + b] = hi;
    }
}

// ============================================================================
// Kernel 6: root finalize: combine 17 partials + bias + tanh + BN stats +
// normalize + write out. grid(38) — one block per output column.
// ============================================================================
__global__ __launch_bounds__(256) void k_rootfin(
    const float* __restrict__ b_root, const float* __restrict__ gam,
    const float* __restrict__ bet, float* __restrict__ out)
{
    const int o = blockIdx.x;
    const int tid = threadIdx.x;
    const float bias = b_root[o];

    float h[8];
    float s1 = 0.f, s2 = 0.f;
#pragma unroll
    for (int w = 0; w < 8; w++) {
        const int b = w * 256 + tid;
        float v = bias;
#pragma unroll
        for (int kc = 0; kc < 17; kc++)
            v += g_root_part[((long)(kc * 40 + o)) * B_ + b];       // coalesced
        const float t = ftanh(v);
        h[w] = t;
        s1 += t; s2 = fmaf(t, t, s2);
    }
    for (int off = 16; off > 0; off >>= 1) {
        s1 += __shfl_down_sync(0xffffffffu, s1, off);
        s2 += __shfl_down_sync(0xffffffffu, s2, off);
    }
    __shared__ float r1[8], r2[8];
    __shared__ float sAC[2];
    if ((tid & 31) == 0) { r1[tid >> 5] = s1; r2[tid >> 5] = s2; }
    __syncthreads();
    if (tid == 0) {
        float t1 = 0.f, t2 = 0.f;
        for (int w = 0; w < 8; w++) { t1 += r1[w]; t2 += r2[w]; }
        const float mean = t1 * (1.f / B_);
        const float var  = t2 * (1.f / B_) - mean * mean;
        const float a = gam[o] * rsqrtf(var + EPSF);
        sAC[0] = a;
        sAC[1] = bet[o] - mean * a;
    }
    __syncthreads();
    const float a = sAC[0], c = sAC[1];
#pragma unroll
    for (int w = 0; w < 8; w++) {
        const int b = w * 256 + tid;
        out[(long)b * OR_ + o] = fmaf(h[w], a, c);
    }
}

// ============================================================================
extern "C" void kernel_launch(void* const* d_in, const int* in_sizes, int n_in,
                              void* d_out, int out_size)
{
    const float* x_leaf = (const float*)d_in[0];
    const float* x_mid  = (const float*)d_in[1];
    const float* x_root = (const float*)d_in[2];
    const float* W_leaf = (const float*)d_in[3];
    const float* b_leaf = (const float*)d_in[4];
    const float* gleaf  = (const float*)d_in[5];
    const float* beleaf = (const float*)d_in[6];
    const float* W_mid  = (const float*)d_in[7];
    const float* b_mid  = (const float*)d_in[8];
    const float* gmid   = (const float*)d_in[9];
    const float* bemid  = (const float*)d_in[10];
    const float* W_root = (const float*)d_in[11];
    const float* b_root = (const float*)d_in[12];
    const float* groot  = (const float*)d_in[13];
    const float* beroot = (const float*)d_in[14];
    float* out = (float*)d_out;

    k_leaf<<<dim3(2, S_), 128>>>(x_leaf, W_leaf, b_leaf);
    k_prep_mid<<<M_, 256>>>(W_mid, b_mid, gleaf, beleaf);
    k_mid<<<dim3(MC_, M_), 128>>>(x_mid);
    k_rootp<<<dim3(16, 16), 128>>>(W_root, gmid, bemid);
    k_rootgene<<<16, 128>>>(x_root, W_root);
    k_rootfin<<<OR_, 256>>>(b_root, groot, beroot, out);
}